// round 1
// baseline (speedup 1.0000x reference)
#include <cuda_runtime.h>
#include <cstdint>

#define NN 100000
#define NE 1000000
#define NB 500000
#define H  16
#define RND 5

// ---------------- scratch (device globals; no allocation allowed) ----------
__device__ __align__(16) float g_nf[NN * H];      // node features [n][16]
__device__ __align__(16) float g_ef[NE * H];      // edge features [e][16]
__device__ __align__(16) float g_pre_s[NN * H];   // W1[:,0:16]  @ nf per node
__device__ __align__(16) float g_pre_r[NN * H];   // W1[:,16:32] @ nf per node (+b1)
__device__ __align__(16) float g_agg[NN * H];     // scatter-sum of new ef per node
__device__ float g_deg[NN];
__device__ int   g_win[NE];                       // bi-averaging winner key

// ---------------- helpers --------------------------------------------------
__device__ __forceinline__ void ld16(const float* __restrict__ p, float* f) {
    const float4* q = (const float4*)p;
    float4 a = q[0], b = q[1], c = q[2], d = q[3];
    f[0]=a.x; f[1]=a.y; f[2]=a.z; f[3]=a.w;
    f[4]=b.x; f[5]=b.y; f[6]=b.z; f[7]=b.w;
    f[8]=c.x; f[9]=c.y; f[10]=c.z; f[11]=c.w;
    f[12]=d.x; f[13]=d.y; f[14]=d.z; f[15]=d.w;
}

__device__ __forceinline__ void st16(float* __restrict__ p, const float* f) {
    float4* q = (float4*)p;
    q[0] = make_float4(f[0], f[1], f[2], f[3]);
    q[1] = make_float4(f[4], f[5], f[6], f[7]);
    q[2] = make_float4(f[8], f[9], f[10], f[11]);
    q[3] = make_float4(f[12], f[13], f[14], f[15]);
}

__device__ __forceinline__ void red_add4(float* p, float x, float y, float z, float w) {
    asm volatile("red.global.add.v4.f32 [%0], {%1,%2,%3,%4};"
                 :: "l"(p), "f"(x), "f"(y), "f"(z), "f"(w) : "memory");
}

// ---------------- kernels --------------------------------------------------
__global__ void k_init() {
    int t = blockIdx.x * blockDim.x + threadIdx.x;
    if (t < NN) g_deg[t] = 0.0f;
    if (t < NE) g_win[t] = -1;
}

// scalar -> h -> h encoder. which==0 writes g_nf, which==1 writes g_ef (+deg count)
__global__ void k_encode(const float* __restrict__ x, int n, int which,
                         const float* __restrict__ W1, const float* __restrict__ b1,
                         const float* __restrict__ W2, const float* __restrict__ b2,
                         const int* __restrict__ recv) {
    __shared__ float sW2[256], sW1[16], sB1[16], sB2[16];
    int tid = threadIdx.x;
    for (int i = tid; i < 256; i += blockDim.x) sW2[i] = W2[i];
    if (tid < 16) { sW1[tid] = W1[tid]; sB1[tid] = b1[tid]; sB2[tid] = b2[tid]; }
    __syncthreads();
    int idx = blockIdx.x * blockDim.x + tid;
    if (idx >= n) return;
    float xv = x[idx];
    float h[16];
#pragma unroll
    for (int k = 0; k < 16; k++) {
        float v = sW1[k] * xv + sB1[k];
        h[k] = fmaxf(v, 0.0f);
    }
    float out[16];
#pragma unroll
    for (int o = 0; o < 16; o++) {
        float acc = sB2[o];
#pragma unroll
        for (int k = 0; k < 16; k++) acc += sW2[o * 16 + k] * h[k];
        out[o] = acc;
    }
    float* dst = which ? &g_ef[(size_t)idx * 16] : &g_nf[(size_t)idx * 16];
    st16(dst, out);
    if (which) atomicAdd(&g_deg[recv[idx]], 1.0f);
}

// per-round node precompute: pre_s = W1[:,0:16]@nf ; pre_r = W1[:,16:32]@nf + b1 ; agg = 0
__global__ void k_node_pre(const float* __restrict__ W1, const float* __restrict__ b1) {
    __shared__ float sW[512], sB1[16];
    int tid = threadIdx.x;
    for (int i = tid; i < 512; i += blockDim.x) {
        int o = i >> 5, k = i & 31;
        sW[i] = W1[o * 48 + k];
    }
    if (tid < 16) sB1[tid] = b1[tid];
    __syncthreads();
    int n = blockIdx.x * blockDim.x + tid;
    if (n >= NN) return;
    float f[16];
    ld16(&g_nf[(size_t)n * 16], f);
    float ps[16], pr[16];
#pragma unroll
    for (int o = 0; o < 16; o++) {
        float a = 0.0f, b = sB1[o];
#pragma unroll
        for (int k = 0; k < 16; k++) {
            a += sW[o * 32 + k] * f[k];
            b += sW[o * 32 + 16 + k] * f[k];
        }
        ps[o] = a; pr[o] = b;
    }
    st16(&g_pre_s[(size_t)n * 16], ps);
    st16(&g_pre_r[(size_t)n * 16], pr);
    float z[16];
#pragma unroll
    for (int o = 0; o < 16; o++) z[o] = 0.0f;
    st16(&g_agg[(size_t)n * 16], z);
}

// per-round edge update (in-place on g_ef) fused with scatter into agg
__global__ void k_edge(const int* __restrict__ snd, const int* __restrict__ rcv,
                       const float* __restrict__ W1, const float* __restrict__ W2,
                       const float* __restrict__ b2) {
    __shared__ float sW1[256], sW2[256], sB2[16];
    int tid = threadIdx.x;
    for (int i = tid; i < 256; i += blockDim.x) {
        int o = i >> 4, k = i & 15;
        sW1[i] = W1[o * 48 + 32 + k];   // ef-part of the 16x48 first layer
        sW2[i] = W2[i];
    }
    if (tid < 16) sB2[tid] = b2[tid];
    __syncthreads();
    int e = blockIdx.x * blockDim.x + tid;
    if (e >= NE) return;
    int s = snd[e], r = rcv[e];
    float xin[16], h1[16], ps[16], pr[16];
    ld16(&g_ef[(size_t)e * 16], xin);
    ld16(&g_pre_s[(size_t)s * 16], ps);
    ld16(&g_pre_r[(size_t)r * 16], pr);
#pragma unroll
    for (int o = 0; o < 16; o++) {
        float acc = ps[o] + pr[o];          // b1 folded into pre_r
#pragma unroll
        for (int k = 0; k < 16; k++) acc += sW1[o * 16 + k] * xin[k];
        h1[o] = fmaxf(acc, 0.0f);
    }
    float out[16];
#pragma unroll
    for (int o = 0; o < 16; o++) {
        float acc = sB2[o];
#pragma unroll
        for (int k = 0; k < 16; k++) acc += sW2[o * 16 + k] * h1[k];
        out[o] = acc;
    }
    st16(&g_ef[(size_t)e * 16], out);
    float* ag = &g_agg[(size_t)r * 16];
    red_add4(ag + 0,  out[0],  out[1],  out[2],  out[3]);
    red_add4(ag + 4,  out[4],  out[5],  out[6],  out[7]);
    red_add4(ag + 8,  out[8],  out[9],  out[10], out[11]);
    red_add4(ag + 12, out[12], out[13], out[14], out[15]);
}

// per-round node update: nf = mlp2([nf; agg/deg])
__global__ void k_node_upd(const float* __restrict__ W1, const float* __restrict__ b1,
                           const float* __restrict__ W2, const float* __restrict__ b2) {
    __shared__ float sW1[512], sW2[256], sB1[16], sB2[16];
    int tid = threadIdx.x;
    for (int i = tid; i < 512; i += blockDim.x) sW1[i] = W1[i];
    for (int i = tid; i < 256; i += blockDim.x) sW2[i] = W2[i];
    if (tid < 16) { sB1[tid] = b1[tid]; sB2[tid] = b2[tid]; }
    __syncthreads();
    int n = blockIdx.x * blockDim.x + tid;
    if (n >= NN) return;
    float f[16], a[16];
    ld16(&g_nf[(size_t)n * 16], f);
    ld16(&g_agg[(size_t)n * 16], a);
    float inv = 1.0f / fmaxf(g_deg[n], 1.0f);
#pragma unroll
    for (int k = 0; k < 16; k++) a[k] *= inv;
    float h1[16];
#pragma unroll
    for (int o = 0; o < 16; o++) {
        float acc = sB1[o];
#pragma unroll
        for (int k = 0; k < 16; k++) {
            acc += sW1[o * 32 + k] * f[k];
            acc += sW1[o * 32 + 16 + k] * a[k];
        }
        h1[o] = fmaxf(acc, 0.0f);
    }
    float out[16];
#pragma unroll
    for (int o = 0; o < 16; o++) {
        float acc = sB2[o];
#pragma unroll
        for (int k = 0; k < 16; k++) acc += sW2[o * 16 + k] * h1[k];
        out[o] = acc;
    }
    st16(&g_nf[(size_t)n * 16], out);
}

// bi-edge averaging phase 1: elect a winner pair per touched edge.
// Sequential-scatter semantics: j-scatter beats i-scatter; within a scatter,
// the larger pair index wins. key = (side<<30) | p, resolved with atomicMax.
__global__ void k_bi(const int* __restrict__ bi) {
    int p = blockIdx.x * blockDim.x + threadIdx.x;
    if (p >= NB) return;
    atomicMax(&g_win[bi[p]], p);
    atomicMax(&g_win[bi[NB + p]], (1 << 30) | p);
}

// decode: resolve bi-average from PRE-update ef (never written), MLP to scalar,
// tril mask, write output (plus optional flattened receivers/senders).
__global__ void k_dec(const int* __restrict__ snd, const int* __restrict__ rcv,
                      const int* __restrict__ bi,
                      const float* __restrict__ W1, const float* __restrict__ b1,
                      const float* __restrict__ W2, const float* __restrict__ b2,
                      float* __restrict__ out, int write_extra) {
    __shared__ float sW1[256], sB1[16], sW2[16], sB2;
    int tid = threadIdx.x;
    for (int i = tid; i < 256; i += blockDim.x) sW1[i] = W1[i];
    if (tid < 16) { sB1[tid] = b1[tid]; sW2[tid] = W2[tid]; }
    if (tid == 0) sB2 = b2[0];
    __syncthreads();
    int e = blockIdx.x * blockDim.x + tid;
    if (e >= NE) return;
    float f[16];
    int w = g_win[e];
    if (w >= 0) {
        int p = w & 0x3FFFFFFF;
        int i = bi[p], j = bi[NB + p];
        float fi[16], fj[16];
        ld16(&g_ef[(size_t)i * 16], fi);
        ld16(&g_ef[(size_t)j * 16], fj);
#pragma unroll
        for (int k = 0; k < 16; k++) f[k] = 0.5f * (fi[k] + fj[k]);
    } else {
        ld16(&g_ef[(size_t)e * 16], f);
    }
    float val = sB2;
#pragma unroll
    for (int o = 0; o < 16; o++) {
        float acc = sB1[o];
#pragma unroll
        for (int k = 0; k < 16; k++) acc += sW1[o * 16 + k] * f[k];
        val += sW2[o] * fmaxf(acc, 0.0f);
    }
    int s = snd[e], r = rcv[e];
    out[e] = (r >= s) ? val : 0.0f;
    if (write_extra) {
        out[NE + e] = (float)r;
        out[2 * NE + e] = (float)s;
    }
}

// ---------------- launch ---------------------------------------------------
extern "C" void kernel_launch(void* const* d_in, const int* in_sizes, int n_in,
                              void* d_out, int out_size) {
    const float* nodes    = (const float*)d_in[0];
    const float* edges    = (const float*)d_in[1];
    const int*   receivers= (const int*)d_in[2];
    const int*   senders  = (const int*)d_in[3];
    const int*   bi       = (const int*)d_in[4];
    const float* neW1 = (const float*)d_in[5];
    const float* neB1 = (const float*)d_in[6];
    const float* neW2 = (const float*)d_in[7];
    const float* neB2 = (const float*)d_in[8];
    const float* eeW1 = (const float*)d_in[9];
    const float* eeB1 = (const float*)d_in[10];
    const float* eeW2 = (const float*)d_in[11];
    const float* eeB2 = (const float*)d_in[12];
    const float* meW1 = (const float*)d_in[13];  // [5][16][48]
    const float* meB1 = (const float*)d_in[14];  // [5][16]
    const float* meW2 = (const float*)d_in[15];  // [5][16][16]
    const float* meB2 = (const float*)d_in[16];  // [5][16]
    const float* mnW1 = (const float*)d_in[17];  // [5][16][32]
    const float* mnB1 = (const float*)d_in[18];
    const float* mnW2 = (const float*)d_in[19];
    const float* mnB2 = (const float*)d_in[20];
    const float* dW1  = (const float*)d_in[21];
    const float* dB1  = (const float*)d_in[22];
    const float* dW2  = (const float*)d_in[23];
    const float* dB2  = (const float*)d_in[24];

    const int TB = 256;
    const int gN = (NN + TB - 1) / TB;
    const int gE = (NE + TB - 1) / TB;
    const int gB = (NB + TB - 1) / TB;

    k_init<<<gE, TB>>>();
    k_encode<<<gN, TB>>>(nodes, NN, 0, neW1, neB1, neW2, neB2, nullptr);
    k_encode<<<gE, TB>>>(edges, NE, 1, eeW1, eeB1, eeW2, eeB2, receivers);

    for (int r = 0; r < RND; r++) {
        k_node_pre<<<gN, TB>>>(meW1 + (size_t)r * 16 * 48, meB1 + (size_t)r * 16);
        k_edge<<<gE, TB>>>(senders, receivers,
                           meW1 + (size_t)r * 16 * 48,
                           meW2 + (size_t)r * 256,
                           meB2 + (size_t)r * 16);
        k_node_upd<<<gN, TB>>>(mnW1 + (size_t)r * 512, mnB1 + (size_t)r * 16,
                               mnW2 + (size_t)r * 256, mnB2 + (size_t)r * 16);
    }

    k_bi<<<gB, TB>>>(bi);
    int write_extra = (out_size >= 3 * NE) ? 1 : 0;
    k_dec<<<gE, TB>>>(senders, receivers, bi, dW1, dB1, dW2, dB2,
                      (float*)d_out, write_extra);
}